// round 14
// baseline (speedup 1.0000x reference)
#include <cuda_runtime.h>
#include <cstdint>
#include <math.h>

#define T 8192
#define C 512
#define II 64
#define E 32
#define KFB (E/2)
#define FULLMASK 0xffffffffu
#define NEGC (-3.3895313892515355e+38f)

// ---------------- device scratch ----------------
__device__ float g_rw[T * E];
__device__ int   g_idx[E * T];
__device__ int   g_iidx[E * T];
__device__ int   g_cnt[E];
__device__ int   g_icnt[E];
__device__ float g_colnorm[E];
__device__ float g_sig[E];
__device__ float g_Xp[(size_t)T * C];         // x, tf32-rounded, perm per 8-k group
__device__ float g_W1t[(size_t)E * II * C];   // [e][i][pk]  K-major, tf32, permuted
__device__ float g_W2t[(size_t)E * C * II];   // [e][c][pk]  K-major, tf32, permuted

#define PCOL(k) (((k) & ~7) | ((((k) & 3) << 1) | (((k) >> 2) & 1)))

// ---------------- helpers ----------------
__device__ __forceinline__ float to_tf32(float f) {
    uint32_t u;
    asm("cvt.rna.tf32.f32 %0, %1;" : "=r"(u) : "f"(f));
    return __uint_as_float(u);
}
__device__ __forceinline__ uint32_t smem_u32(const void* p) {
    uint32_t a;
    asm("{ .reg .u64 t; cvta.to.shared.u64 t, %1; cvt.u32.u64 %0, t; }" : "=r"(a) : "l"(p));
    return a;
}
__device__ __forceinline__ void cpa16(uint32_t dst, const void* src, bool valid) {
    int sz = valid ? 16 : 0;
    asm volatile("cp.async.cg.shared.global [%0], [%1], 16, %2;"
                 :: "r"(dst), "l"(src), "r"(sz) : "memory");
}
#define CP_COMMIT() asm volatile("cp.async.commit_group;" ::: "memory")
#define CP_WAIT(n)  asm volatile("cp.async.wait_group %0;" :: "n"(n) : "memory")

__device__ __forceinline__ void mma16n8k8(float* d, const uint32_t* a, const uint32_t* b) {
    asm volatile(
        "mma.sync.aligned.m16n8k8.row.col.f32.tf32.tf32.f32 "
        "{%0,%1,%2,%3}, {%4,%5,%6,%7}, {%8,%9}, {%0,%1,%2,%3};"
        : "+f"(d[0]), "+f"(d[1]), "+f"(d[2]), "+f"(d[3])
        : "r"(a[0]), "r"(a[1]), "r"(a[2]), "r"(a[3]), "r"(b[0]), "r"(b[1]));
}

__device__ __forceinline__ float gelu_exact(float v) {
    return 0.5f * v * (1.0f + erff(v * 0.70710678118654752f));
}

// ---------------- launch 1: prep ----------------
__global__ void prep_kernel(const float* __restrict__ sim, const float* __restrict__ gates) {
    int w = threadIdx.x >> 5;
    int lane = threadIdx.x & 31;
    float s = 0.f;
    for (int c = lane; c < C; c += 32) {
        float v = sim[c * E + w];
        s = fmaf(v, v, s);
    }
    #pragma unroll
    for (int o = 16; o; o >>= 1) s += __shfl_xor_sync(FULLMASK, s, o);
    if (lane == 0) {
        g_colnorm[w] = fmaxf(sqrtf(s), 1e-12f);
        g_sig[w]     = 1.f / (1.f + expf(-gates[w]));
        g_cnt[w]     = 0;
        g_icnt[w]    = 0;
    }
}

// ---------------- launch 2: fused preprocessing megakernel ----------------
#define GB_GATE 1024
#define GB_TW1  (GB_GATE + 1024)
#define GB_TW2  (GB_TW1 + 1024)
#define GB_RX   (GB_TW2 + 4096)

__global__ __launch_bounds__(256) void fused_pre(
    const float* __restrict__ x, const float* __restrict__ sim,
    const float* __restrict__ W1, const float* __restrict__ W2,
    float* __restrict__ pre_out, float* __restrict__ mask_out) {
    __shared__ float s_x[8 * C];
    __shared__ unsigned char s_act[8][E];

    int b = blockIdx.x;
    int tid = threadIdx.x;

    if (b >= GB_TW2) {
        // round_x role
        int b2 = b - GB_TW2;
        int t = b2 * 2 + (tid >> 7);
        int c = (tid & 127) * 4;
        float4 v = *(const float4*)(x + (size_t)t * C + c);
        float* dst = g_Xp + (size_t)t * C;
        dst[PCOL(c)]     = to_tf32(v.x);
        dst[PCOL(c + 1)] = to_tf32(v.y);
        dst[PCOL(c + 2)] = to_tf32(v.z);
        dst[PCOL(c + 3)] = to_tf32(v.w);
        return;
    }
    if (b >= GB_GATE) {
        // weight transpose roles
        float (*t)[33] = (float(*)[33])s_x;
        int tx = tid & 31, ty = tid >> 5;
        if (b < GB_TW1) {
            int b2 = b - GB_GATE;
            int c0 = (b2 & 15) * 32, i0 = ((b2 >> 4) & 1) * 32, e = b2 >> 5;
            #pragma unroll
            for (int j = 0; j < 32; j += 8)
                t[ty + j][tx] = W1[((size_t)e * C + c0 + ty + j) * II + i0 + tx];
            __syncthreads();
            #pragma unroll
            for (int j = 0; j < 32; j += 8)
                g_W1t[((size_t)e * II + i0 + ty + j) * C + PCOL(c0 + tx)] = to_tf32(t[tx][ty + j]);
        } else {
            int b2 = b - GB_TW1;
            int i0 = (b2 & 1) * 32, c0 = ((b2 >> 1) & 15) * 32, e = b2 >> 5;
            #pragma unroll
            for (int j = 0; j < 32; j += 8)
                t[ty + j][tx] = W2[((size_t)e * II + i0 + ty + j) * C + c0 + tx];
            __syncthreads();
            #pragma unroll
            for (int j = 0; j < 32; j += 8)
                g_W2t[((size_t)e * C + c0 + ty + j) * II + PCOL(i0 + tx)] = to_tf32(t[tx][ty + j]);
        }
        return;
    }

    // gating role
    int w = tid >> 5;
    int lane = tid & 31;
    int t0 = b * 8;
    int t = t0 + w;

    const float* xbase = x + (size_t)t0 * C;
    #pragma unroll
    for (int p = 0; p < 16; p++) s_x[tid + p * 256] = xbase[tid + p * 256];
    __syncthreads();

    const float* xw = s_x + w * C;
    float acc = 0.f, nsq = 0.f;
    #pragma unroll 8
    for (int c = 0; c < C; c++) {
        float xc = xw[c];
        acc = fmaf(xc, __ldg(&sim[c * E + lane]), acc);
        nsq = fmaf(xc, xc, nsq);
    }

    float xnorm = fmaxf(sqrtf(nsq), 1e-12f);
    float logit = acc / (xnorm * g_colnorm[lane]);
    float pre   = logit - g_sig[lane];
    float gated = fmaxf(pre, 0.f);

    unsigned act = __ballot_sync(FULLMASK, gated > 0.f);
    float maskv;
    if (act == 0u) {
        int rank = 0;
        #pragma unroll
        for (int j = 0; j < 32; j++) {
            float lj = __shfl_sync(FULLMASK, logit, j);
            rank += (lj > logit) || (lj == logit && j < lane);
        }
        maskv = (rank < KFB) ? 1.f : 0.f;
    } else {
        maskv = (gated > 0.f) ? 1.f : 0.f;
    }

    float maskedv = (maskv > 0.f) ? gated : NEGC;
    float m = maskedv;
    #pragma unroll
    for (int o = 16; o; o >>= 1) m = fmaxf(m, __shfl_xor_sync(FULLMASK, m, o));
    float p = expf(maskedv - m);
    float ssum = p;
    #pragma unroll
    for (int o = 16; o; o >>= 1) ssum += __shfl_xor_sync(FULLMASK, ssum, o);
    float rw = p / ssum;

    pre_out[t * E + lane]  = pre;
    mask_out[t * E + lane] = maskv;
    g_rw[t * E + lane]     = rw;
    s_act[w][lane] = (maskv > 0.f) ? 1 : 0;
    __syncthreads();

    if (tid < E) {
        int e = tid;
        int cntl = 0;
        #pragma unroll
        for (int s2 = 0; s2 < 8; s2++) cntl += s_act[s2][e];
        if (cntl > 0) {
            int base = atomicAdd(&g_cnt[e], cntl);
            for (int s2 = 0; s2 < 8; s2++)
                if (s_act[s2][e]) g_idx[e * T + base++] = t0 + s2;
        }
        if (cntl < 8) {
            int ibase = atomicAdd(&g_icnt[e], 8 - cntl);
            for (int s2 = 0; s2 < 8; s2++)
                if (!s_act[s2][e]) g_iidx[e * T + ibase++] = t0 + s2;
        }
    }
}

// ---------------- launch 3: fused expert MLP (R12 layout; H-in-regs phase 2) ------
#define MS1 40
#define MSH 72
#define XBUF_B (128 * MS1 * 4)              // 20480
#define W1BUF_B (64 * MS1 * 4)              // 10240
#define OFF_A0 1024
#define OFF_W  (1024 + 2 * XBUF_B)          // 41984
#define EM_SMEM (OFF_W + 2 * W1BUF_B)       // 62464

__global__ __launch_bounds__(256, 2) void expert_mlp(float* __restrict__ feo) {
    int e = blockIdx.y;
    int cnt = g_cnt[e];
    int cntB = (cnt + 127) >> 7;
    int tid = threadIdx.x;

    extern __shared__ char smem[];
    int* toks = (int*)smem;

    if ((int)blockIdx.x >= cntB) {
        int icnt = g_icnt[e];
        int zi0 = ((int)blockIdx.x - cntB) * 128;
        if (zi0 >= icnt) return;
        int nrows = min(128, icnt - zi0);
        if (tid < nrows) toks[tid] = g_iidx[e * T + zi0 + tid];
        __syncthreads();
        float4 z = make_float4(0.f, 0.f, 0.f, 0.f);
        for (int j = tid; j < nrows * 128; j += 256) {
            int r = j >> 7, q = j & 127;
            ((float4*)&feo[((size_t)toks[r] * E + e) * C])[q] = z;
        }
        return;
    }

    int m0 = blockIdx.x * 128;
    uint32_t sb = smem_u32(smem);
    int wid = tid >> 5, lane = tid & 31;
    if (tid < 128) toks[tid] = (m0 + tid < cnt) ? g_idx[e * T + m0 + tid] : -1;
    __syncthreads();

    int warpM = wid >> 1, warpN = wid & 1;
    int rbase = warpM * 32;
    int lr = lane >> 2, lc = lane & 3;

    uint32_t aoff[2] = { sb + OFF_A0, sb + OFF_A0 + XBUF_B };
    uint32_t boff[2] = { sb + OFF_W, sb + OFF_W + W1BUF_B };

    auto stage1 = [&](int kc, int b) {
        #pragma unroll
        for (int p = 0; p < 4; p++) {
            int idx = tid + (p << 8);
            int r = idx >> 3, q = idx & 7;
            int tok = toks[r];
            const float* src = g_Xp + (size_t)(tok < 0 ? 0 : tok) * C + kc * 32 + q * 4;
            cpa16(aoff[b] + r * (MS1 * 4) + q * 16, src, tok >= 0);
        }
        #pragma unroll
        for (int p = 0; p < 2; p++) {
            int idx = tid + (p << 8);
            int i = idx >> 3, q = idx & 7;
            const float* src = g_W1t + ((size_t)e * II + i) * C + kc * 32 + q * 4;
            cpa16(boff[b] + i * (MS1 * 4) + q * 16, src, true);
        }
        CP_COMMIT();
    };

    // ---------- phase 1: 16 k-chunks of 32, double-buffered ----------
    {
        int nbase = warpN * 32;
        float d[2][4][4];
        #pragma unroll
        for (int mt = 0; mt < 2; mt++)
            #pragma unroll
            for (int nt = 0; nt < 4; nt++)
                #pragma unroll
                for (int i = 0; i < 4; i++) d[mt][nt][i] = 0.f;

        stage1(0, 0);
        #pragma unroll 1
        for (int kc = 0; kc < 16; kc++) {
            if (kc + 1 < 16) { stage1(kc + 1, (kc + 1) & 1); CP_WAIT(1); }
            else             { CP_WAIT(0); }
            __syncthreads();

            float* Ab = (float*)(smem + OFF_A0 + (kc & 1) * XBUF_B);
            float* Bb = (float*)(smem + OFF_W + (kc & 1) * W1BUF_B);

            #pragma unroll
            for (int ks = 0; ks < 4; ks++) {
                int k0 = ks * 8;
                uint32_t afr[2][4], bfr[4][2];
                #pragma unroll
                for (int mt = 0; mt < 2; mt++) {
                    int row = rbase + mt * 16 + lr;
                    float2 pa0 = *(float2*)(Ab + row * MS1 + k0 + lc * 2);
                    float2 pa1 = *(float2*)(Ab + (row + 8) * MS1 + k0 + lc * 2);
                    afr[mt][0] = __float_as_uint(pa0.x);
                    afr[mt][1] = __float_as_uint(pa1.x);
                    afr[mt][2] = __float_as_uint(pa0.y);
                    afr[mt][3] = __float_as_uint(pa1.y);
                }
                #pragma unroll
                for (int nt = 0; nt < 4; nt++) {
                    int col = nbase + nt * 8 + lr;
                    float2 pb = *(float2*)(Bb + col * MS1 + k0 + lc * 2);
                    bfr[nt][0] = __float_as_uint(pb.x);
                    bfr[nt][1] = __float_as_uint(pb.y);
                }
                #pragma unroll
                for (int mt = 0; mt < 2; mt++)
                    #pragma unroll
                    for (int nt = 0; nt < 4; nt++)
                        mma16n8k8(d[mt][nt], afr[mt], bfr[nt]);
            }
            __syncthreads();
        }

        // prefetch W2 chunk 0
        {
            #pragma unroll
            for (int p = 0; p < 4; p++) {
                int idx = tid + (p << 8);
                int n = idx >> 4, q = idx & 15;
                const float* src = g_W2t + ((size_t)e * C + n) * II + q * 4;
                cpa16(sb + OFF_W + n * (MSH * 4) + q * 16, src, true);
            }
            CP_COMMIT();
        }

        // H epilogue -> A region (stride MSH, permuted)
        float* H = (float*)(smem + OFF_A0);
        int pos0 = ((lc & 1) << 2) | (lc >> 1);
        #pragma unroll
        for (int mt = 0; mt < 2; mt++) {
            int r0 = rbase + mt * 16 + lr;
            #pragma unroll
            for (int nt = 0; nt < 4; nt++) {
                int base = nbase + nt * 8;
                H[r0 * MSH + base + pos0]           = to_tf32(gelu_exact(d[mt][nt][0]));
                H[r0 * MSH + base + pos0 + 2]       = to_tf32(gelu_exact(d[mt][nt][1]));
                H[(r0 + 8) * MSH + base + pos0]     = to_tf32(gelu_exact(d[mt][nt][2]));
                H[(r0 + 8) * MSH + base + pos0 + 2] = to_tf32(gelu_exact(d[mt][nt][3]));
            }
        }
    }
    __syncthreads();   // H visible to all warps

    // ---------- preload ALL H fragments into registers (once) ----------
    float* H = (float*)(smem + OFF_A0);
    uint32_t hreg[8][8];   // [ks][mt*4 + j]
    #pragma unroll
    for (int ks = 0; ks < 8; ks++) {
        int k0 = ks * 8;
        #pragma unroll
        for (int mt = 0; mt < 2; mt++) {
            int row = rbase + mt * 16 + lr;
            float2 pa0 = *(float2*)(H + row * MSH + k0 + lc * 2);
            float2 pa1 = *(float2*)(H + (row + 8) * MSH + k0 + lc * 2);
            hreg[ks][mt * 4 + 0] = __float_as_uint(pa0.x);
            hreg[ks][mt * 4 + 1] = __float_as_uint(pa1.x);
            hreg[ks][mt * 4 + 2] = __float_as_uint(pa0.y);
            hreg[ks][mt * 4 + 3] = __float_as_uint(pa1.y);
        }
    }

    // ---------- phase 2: 8 n-chunks of 64 cols, W2-only LDS ----------
    float* Wb = (float*)(smem + OFF_W);
    int nbase2 = warpN * 32;

    auto stage2 = [&](int nc) {
        #pragma unroll
        for (int p = 0; p < 4; p++) {
            int idx = tid + (p << 8);
            int n = idx >> 4, q = idx & 15;
            const float* src = g_W2t + ((size_t)e * C + nc * 64 + n) * II + q * 4;
            cpa16(sb + OFF_W + n * (MSH * 4) + q * 16, src, true);
        }
        CP_COMMIT();
    };

    #pragma unroll 1
    for (int nc = 0; nc < 8; nc++) {
        CP_WAIT(0);
        __syncthreads();   // W2 chunk nc visible

        float d2[2][4][4];
        #pragma unroll
        for (int mt = 0; mt < 2; mt++)
            #pragma unroll
            for (int nt = 0; nt < 4; nt++)
                #pragma unroll
                for (int i = 0; i < 4; i++) d2[mt][nt][i] = 0.f;

        #pragma unroll
        for (int ks = 0; ks < 8; ks++) {
            int k0 = ks * 8;
            uint32_t bfr[4][2];
            #pragma unroll
            for (int nt = 0; nt < 4; nt++) {
                int col = nbase2 + nt * 8 + lr;
                float2 pb = *(float2*)(Wb + col * MSH + k0 + lc * 2);
                bfr[nt][0] = __float_as_uint(pb.x);
                bfr[nt][1] = __float_as_uint(pb.y);
            }
            #pragma unroll
            for (int mt = 0; mt < 2; mt++)
                #pragma unroll
                for (int nt = 0; nt < 4; nt++)
                    mma16n8k8(d2[mt][nt], &hreg[ks][mt * 4], bfr[nt]);
        }

        __syncthreads();            // reads of W2 chunk nc done
        if (nc + 1 < 8) stage2(nc + 1);

        #pragma unroll
        for (int mt = 0; mt < 2; mt++) {
            int s0 = rbase + mt * 16 + lr, s1 = s0 + 8;
            int tok0 = toks[s0], tok1 = toks[s1];
            #pragma unroll
            for (int nt = 0; nt < 4; nt++) {
                int col = nc * 64 + nbase2 + nt * 8 + lc * 2;
                if (tok0 >= 0)
                    *(float2*)&feo[((size_t)tok0 * E + e) * C + col] =
                        make_float2(d2[mt][nt][0], d2[mt][nt][1]);
                if (tok1 >= 0)
                    *(float2*)&feo[((size_t)tok1 * E + e) * C + col] =
                        make_float2(d2[mt][nt][2], d2[mt][nt][3]);
            }
        }
    }
}

// ---------------- launch 4: final reduce (2 tokens / 256-thread block) ------------
__global__ __launch_bounds__(256) void final_reduce(
    const float* __restrict__ maskp, const float* __restrict__ feo,
    float* __restrict__ final_out) {
    int half = threadIdx.x >> 7;              // 0 or 1
    int stid = threadIdx.x & 127;
    int t = blockIdx.x * 2 + half;
    int lane = threadIdx.x & 31;
    __shared__ float s_w[2][E];
    __shared__ int   s_ei[2][E];
    __shared__ int   s_na[2];

    if (stid < 32) {                          // first warp of each half
        float mv = maskp[(size_t)t * E + lane];
        unsigned act = __ballot_sync(FULLMASK, mv > 0.f);
        int rank = __popc(act & ((1u << lane) - 1u));
        if (mv > 0.f) {
            s_ei[half][rank] = lane;
            s_w[half][rank]  = g_rw[t * E + lane];
        }
        if (lane == 0) s_na[half] = __popc(act);
    }
    __syncthreads();

    int na = s_na[half];
    const float4* base = (const float4*)&feo[(size_t)t * E * C];
    float4 a0 = make_float4(0.f, 0.f, 0.f, 0.f), a1 = a0, a2 = a0, a3 = a0;
    int i = 0;
    for (; i + 4 <= na; i += 4) {
        float w0 = s_w[half][i], w1 = s_w[half][i + 1];
        float w2 = s_w[half][i + 2], w3 = s_w[half][i + 3];
        float4 v0 = base[s_ei[half][i]     * 128 + stid];
        float4 v1 = base[s_ei[half][i + 1] * 128 + stid];
        float4 v2 = base[s_ei[half][i + 2] * 128 + stid];
        float4 v3 = base[s_ei[half][i + 3] * 128 + stid];
        a0.x = fmaf(w0, v0.x, a0.x); a0.y = fmaf(w0, v0.y, a0.y);
        a0.z = fmaf(w0, v0.z, a0.z); a0.w = fmaf(w0, v0.w, a0.w);
        a1.x = fmaf(w1, v1.x, a1.x); a1.y = fmaf(w1, v1.y, a1.y);
        a1.z = fmaf(w1, v1.z, a1.z); a1.w = fmaf(w1, v1.w, a1.w);
        a2.x = fmaf(w2, v2.x, a2.x); a2.y = fmaf(w2, v2.y, a2.y);
        a2.z = fmaf(w2, v2.z, a2.z); a2.w = fmaf(w2, v2.w, a2.w);
        a3.x = fmaf(w3, v3.x, a3.x); a3.y = fmaf(w3, v3.y, a3.y);
        a3.z = fmaf(w3, v3.z, a3.z); a3.w = fmaf(w3, v3.w, a3.w);
    }
    for (; i < na; i++) {
        float w0 = s_w[half][i];
        float4 v0 = base[s_ei[half][i] * 128 + stid];
        a0.x = fmaf(w0, v0.x, a0.x); a0.y = fmaf(w0, v0.y, a0.y);
        a0.z = fmaf(w0, v0.z, a0.z); a0.w = fmaf(w0, v0.w, a0.w);
    }
    float4 acc;
    acc.x = (a0.x + a1.x) + (a2.x + a3.x);
    acc.y = (a0.y + a1.y) + (a2.y + a3.y);
    acc.z = (a0.z + a1.z) + (a2.z + a3.z);
    acc.w = (a0.w + a1.w) + (a2.w + a3.w);
    ((float4*)&final_out[(size_t)t * C])[stid] = acc;
}

// ---------------- launch ----------------
extern "C" void kernel_launch(void* const* d_in, const int* in_sizes, int n_in,
                              void* d_out, int out_size) {
    const float* x     = (const float*)d_in[0];
    const float* sim   = (const float*)d_in[1];
    const float* gates = (const float*)d_in[2];
    const float* W1    = (const float*)d_in[3];
    const float* W2    = (const float*)d_in[4];

    float* out       = (float*)d_out;
    float* final_out = out;
    float* feo       = out + (size_t)T * C;
    float* pre       = feo + (size_t)T * E * C;
    float* maskp     = pre + (size_t)T * E;

    cudaFuncSetAttribute(expert_mlp, cudaFuncAttributeMaxDynamicSharedMemorySize, EM_SMEM);

    prep_kernel<<<1, 1024>>>(sim, gates);
    fused_pre<<<GB_RX, 256>>>(x, sim, W1, W2, pre, maskp);
    expert_mlp<<<dim3(T / 128 + 1, E), 256, EM_SMEM>>>(feo);
    final_reduce<<<T / 2, 256>>>(maskp, feo, final_out);
}

// round 15
// speedup vs baseline: 1.0031x; 1.0031x over previous
#include <cuda_runtime.h>
#include <cstdint>
#include <math.h>

#define T 8192
#define C 512
#define II 64
#define E 32
#define KFB (E/2)
#define FULLMASK 0xffffffffu
#define NEGC (-3.3895313892515355e+38f)

// ---------------- device scratch ----------------
__device__ float g_rw[T * E];
__device__ int   g_idx[E * T];
__device__ int   g_iidx[E * T];
__device__ int   g_cnt[E];
__device__ int   g_icnt[E];
__device__ float g_colnorm[E];
__device__ float g_sig[E];
__device__ float g_Xp[(size_t)T * C];         // x, tf32-rounded, perm per 8-k group
__device__ float g_W1t[(size_t)E * II * C];   // [e][i][pk]  K-major, tf32, permuted
__device__ float g_W2t[(size_t)E * C * II];   // [e][c][pk]  K-major, tf32, permuted

#define PCOL(k) (((k) & ~7) | ((((k) & 3) << 1) | (((k) >> 2) & 1)))

// ---------------- helpers ----------------
__device__ __forceinline__ float to_tf32(float f) {
    uint32_t u;
    asm("cvt.rna.tf32.f32 %0, %1;" : "=r"(u) : "f"(f));
    return __uint_as_float(u);
}
__device__ __forceinline__ uint32_t smem_u32(const void* p) {
    uint32_t a;
    asm("{ .reg .u64 t; cvta.to.shared.u64 t, %1; cvt.u32.u64 %0, t; }" : "=r"(a) : "l"(p));
    return a;
}
__device__ __forceinline__ void cpa16(uint32_t dst, const void* src, bool valid) {
    int sz = valid ? 16 : 0;
    asm volatile("cp.async.cg.shared.global [%0], [%1], 16, %2;"
                 :: "r"(dst), "l"(src), "r"(sz) : "memory");
}
#define CP_COMMIT() asm volatile("cp.async.commit_group;" ::: "memory")
#define CP_WAIT(n)  asm volatile("cp.async.wait_group %0;" :: "n"(n) : "memory")

__device__ __forceinline__ void mma16n8k8(float* d, const uint32_t* a, const uint32_t* b) {
    asm volatile(
        "mma.sync.aligned.m16n8k8.row.col.f32.tf32.tf32.f32 "
        "{%0,%1,%2,%3}, {%4,%5,%6,%7}, {%8,%9}, {%0,%1,%2,%3};"
        : "+f"(d[0]), "+f"(d[1]), "+f"(d[2]), "+f"(d[3])
        : "r"(a[0]), "r"(a[1]), "r"(a[2]), "r"(a[3]), "r"(b[0]), "r"(b[1]));
}

__device__ __forceinline__ float gelu_exact(float v) {
    return 0.5f * v * (1.0f + erff(v * 0.70710678118654752f));
}

// ---------------- launch 1: prep ----------------
__global__ void prep_kernel(const float* __restrict__ sim, const float* __restrict__ gates) {
    int w = threadIdx.x >> 5;
    int lane = threadIdx.x & 31;
    float s = 0.f;
    for (int c = lane; c < C; c += 32) {
        float v = sim[c * E + w];
        s = fmaf(v, v, s);
    }
    #pragma unroll
    for (int o = 16; o; o >>= 1) s += __shfl_xor_sync(FULLMASK, s, o);
    if (lane == 0) {
        g_colnorm[w] = fmaxf(sqrtf(s), 1e-12f);
        g_sig[w]     = 1.f / (1.f + expf(-gates[w]));
        g_cnt[w]     = 0;
        g_icnt[w]    = 0;
    }
}

// ---------------- launch 2: fused preprocessing megakernel ----------------
#define GB_GATE 1024
#define GB_TW1  (GB_GATE + 1024)
#define GB_TW2  (GB_TW1 + 1024)
#define GB_RX   (GB_TW2 + 4096)

__global__ __launch_bounds__(256) void fused_pre(
    const float* __restrict__ x, const float* __restrict__ sim,
    const float* __restrict__ W1, const float* __restrict__ W2,
    float* __restrict__ pre_out, float* __restrict__ mask_out) {
    __shared__ float s_x[8 * C];
    __shared__ unsigned char s_act[8][E];

    int b = blockIdx.x;
    int tid = threadIdx.x;

    if (b >= GB_TW2) {
        // round_x role
        int b2 = b - GB_TW2;
        int t = b2 * 2 + (tid >> 7);
        int c = (tid & 127) * 4;
        float4 v = *(const float4*)(x + (size_t)t * C + c);
        float* dst = g_Xp + (size_t)t * C;
        dst[PCOL(c)]     = to_tf32(v.x);
        dst[PCOL(c + 1)] = to_tf32(v.y);
        dst[PCOL(c + 2)] = to_tf32(v.z);
        dst[PCOL(c + 3)] = to_tf32(v.w);
        return;
    }
    if (b >= GB_GATE) {
        // weight transpose roles
        float (*t)[33] = (float(*)[33])s_x;
        int tx = tid & 31, ty = tid >> 5;
        if (b < GB_TW1) {
            int b2 = b - GB_GATE;
            int c0 = (b2 & 15) * 32, i0 = ((b2 >> 4) & 1) * 32, e = b2 >> 5;
            #pragma unroll
            for (int j = 0; j < 32; j += 8)
                t[ty + j][tx] = W1[((size_t)e * C + c0 + ty + j) * II + i0 + tx];
            __syncthreads();
            #pragma unroll
            for (int j = 0; j < 32; j += 8)
                g_W1t[((size_t)e * II + i0 + ty + j) * C + PCOL(c0 + tx)] = to_tf32(t[tx][ty + j]);
        } else {
            int b2 = b - GB_TW1;
            int i0 = (b2 & 1) * 32, c0 = ((b2 >> 1) & 15) * 32, e = b2 >> 5;
            #pragma unroll
            for (int j = 0; j < 32; j += 8)
                t[ty + j][tx] = W2[((size_t)e * II + i0 + ty + j) * C + c0 + tx];
            __syncthreads();
            #pragma unroll
            for (int j = 0; j < 32; j += 8)
                g_W2t[((size_t)e * C + c0 + ty + j) * II + PCOL(i0 + tx)] = to_tf32(t[tx][ty + j]);
        }
        return;
    }

    // ---------------- gating role (hoisted norm + 4-way dot ILP) ----------------
    int w = tid >> 5;
    int lane = tid & 31;
    int t0 = b * 8;
    int t = t0 + w;

    const float* xbase = x + (size_t)t0 * C;
    #pragma unroll
    for (int p = 0; p < 16; p++) s_x[tid + p * 256] = xbase[tid + p * 256];
    __syncthreads();

    const float* xw = s_x + w * C;

    // token norm: per-lane strided partial + shuffle reduce (one chain of 16)
    float nsq = 0.f;
    #pragma unroll
    for (int j = 0; j < 16; j++) {
        float v = xw[lane + j * 32];
        nsq = fmaf(v, v, nsq);
    }
    #pragma unroll
    for (int o = 16; o; o >>= 1) nsq += __shfl_xor_sync(FULLMASK, nsq, o);
    float xnorm = fmaxf(sqrtf(nsq), 1e-12f);

    // dot: 4 independent accumulator chains; lane == expert
    float a0 = 0.f, a1 = 0.f, a2 = 0.f, a3 = 0.f;
    #pragma unroll 4
    for (int c = 0; c < C; c += 4) {
        a0 = fmaf(xw[c],     __ldg(&sim[(c)     * E + lane]), a0);
        a1 = fmaf(xw[c + 1], __ldg(&sim[(c + 1) * E + lane]), a1);
        a2 = fmaf(xw[c + 2], __ldg(&sim[(c + 2) * E + lane]), a2);
        a3 = fmaf(xw[c + 3], __ldg(&sim[(c + 3) * E + lane]), a3);
    }
    float acc = (a0 + a1) + (a2 + a3);

    float logit = acc / (xnorm * g_colnorm[lane]);
    float pre   = logit - g_sig[lane];
    float gated = fmaxf(pre, 0.f);

    unsigned act = __ballot_sync(FULLMASK, gated > 0.f);
    float maskv;
    if (act == 0u) {
        int rank = 0;
        #pragma unroll
        for (int j = 0; j < 32; j++) {
            float lj = __shfl_sync(FULLMASK, logit, j);
            rank += (lj > logit) || (lj == logit && j < lane);
        }
        maskv = (rank < KFB) ? 1.f : 0.f;
    } else {
        maskv = (gated > 0.f) ? 1.f : 0.f;
    }

    float maskedv = (maskv > 0.f) ? gated : NEGC;
    float m = maskedv;
    #pragma unroll
    for (int o = 16; o; o >>= 1) m = fmaxf(m, __shfl_xor_sync(FULLMASK, m, o));
    float p = expf(maskedv - m);
    float ssum = p;
    #pragma unroll
    for (int o = 16; o; o >>= 1) ssum += __shfl_xor_sync(FULLMASK, ssum, o);
    float rw = p / ssum;

    pre_out[t * E + lane]  = pre;
    mask_out[t * E + lane] = maskv;
    g_rw[t * E + lane]     = rw;
    s_act[w][lane] = (maskv > 0.f) ? 1 : 0;
    __syncthreads();

    if (tid < E) {
        int e = tid;
        int cntl = 0;
        #pragma unroll
        for (int s2 = 0; s2 < 8; s2++) cntl += s_act[s2][e];
        if (cntl > 0) {
            int base = atomicAdd(&g_cnt[e], cntl);
            for (int s2 = 0; s2 < 8; s2++)
                if (s_act[s2][e]) g_idx[e * T + base++] = t0 + s2;
        }
        if (cntl < 8) {
            int ibase = atomicAdd(&g_icnt[e], 8 - cntl);
            for (int s2 = 0; s2 < 8; s2++)
                if (!s_act[s2][e]) g_iidx[e * T + ibase++] = t0 + s2;
        }
    }
}

// ---------------- launch 3: fused expert MLP (R12/R11 winner, unchanged) ----------
#define MS1 40
#define MSH 72
#define XBUF_B (128 * MS1 * 4)              // 20480
#define W1BUF_B (64 * MS1 * 4)              // 10240
#define OFF_A0 1024
#define OFF_W  (1024 + 2 * XBUF_B)          // 41984
#define EM_SMEM (OFF_W + 2 * W1BUF_B)       // 62464

__global__ __launch_bounds__(256, 3) void expert_mlp(float* __restrict__ feo) {
    int e = blockIdx.y;
    int cnt = g_cnt[e];
    int cntB = (cnt + 127) >> 7;
    int tid = threadIdx.x;

    extern __shared__ char smem[];
    int* toks = (int*)smem;

    if ((int)blockIdx.x >= cntB) {
        int icnt = g_icnt[e];
        int zi0 = ((int)blockIdx.x - cntB) * 128;
        if (zi0 >= icnt) return;
        int nrows = min(128, icnt - zi0);
        if (tid < nrows) toks[tid] = g_iidx[e * T + zi0 + tid];
        __syncthreads();
        float4 z = make_float4(0.f, 0.f, 0.f, 0.f);
        for (int j = tid; j < nrows * 128; j += 256) {
            int r = j >> 7, q = j & 127;
            ((float4*)&feo[((size_t)toks[r] * E + e) * C])[q] = z;
        }
        return;
    }

    int m0 = blockIdx.x * 128;
    uint32_t sb = smem_u32(smem);
    int wid = tid >> 5, lane = tid & 31;
    if (tid < 128) toks[tid] = (m0 + tid < cnt) ? g_idx[e * T + m0 + tid] : -1;
    __syncthreads();

    int warpM = wid >> 1, warpN = wid & 1;
    int rbase = warpM * 32;
    int lr = lane >> 2, lc = lane & 3;

    uint32_t aoff[2] = { sb + OFF_A0, sb + OFF_A0 + XBUF_B };
    uint32_t boff[2] = { sb + OFF_W, sb + OFF_W + W1BUF_B };

    auto stage1 = [&](int kc, int b) {
        #pragma unroll
        for (int p = 0; p < 4; p++) {
            int idx = tid + (p << 8);
            int r = idx >> 3, q = idx & 7;
            int tok = toks[r];
            const float* src = g_Xp + (size_t)(tok < 0 ? 0 : tok) * C + kc * 32 + q * 4;
            cpa16(aoff[b] + r * (MS1 * 4) + q * 16, src, tok >= 0);
        }
        #pragma unroll
        for (int p = 0; p < 2; p++) {
            int idx = tid + (p << 8);
            int i = idx >> 3, q = idx & 7;
            const float* src = g_W1t + ((size_t)e * II + i) * C + kc * 32 + q * 4;
            cpa16(boff[b] + i * (MS1 * 4) + q * 16, src, true);
        }
        CP_COMMIT();
    };

    // ---------- phase 1: 16 k-chunks of 32, double-buffered ----------
    {
        int nbase = warpN * 32;
        float d[2][4][4];
        #pragma unroll
        for (int mt = 0; mt < 2; mt++)
            #pragma unroll
            for (int nt = 0; nt < 4; nt++)
                #pragma unroll
                for (int i = 0; i < 4; i++) d[mt][nt][i] = 0.f;

        stage1(0, 0);
        #pragma unroll 1
        for (int kc = 0; kc < 16; kc++) {
            if (kc + 1 < 16) { stage1(kc + 1, (kc + 1) & 1); CP_WAIT(1); }
            else             { CP_WAIT(0); }
            __syncthreads();

            float* Ab = (float*)(smem + OFF_A0 + (kc & 1) * XBUF_B);
            float* Bb = (float*)(smem + OFF_W + (kc & 1) * W1BUF_B);

            #pragma unroll
            for (int ks = 0; ks < 4; ks++) {
                int k0 = ks * 8;
                uint32_t afr[2][4], bfr[4][2];
                #pragma unroll
                for (int mt = 0; mt < 2; mt++) {
                    int row = rbase + mt * 16 + lr;
                    float2 pa0 = *(float2*)(Ab + row * MS1 + k0 + lc * 2);
                    float2 pa1 = *(float2*)(Ab + (row + 8) * MS1 + k0 + lc * 2);
                    afr[mt][0] = __float_as_uint(pa0.x);
                    afr[mt][1] = __float_as_uint(pa1.x);
                    afr[mt][2] = __float_as_uint(pa0.y);
                    afr[mt][3] = __float_as_uint(pa1.y);
                }
                #pragma unroll
                for (int nt = 0; nt < 4; nt++) {
                    int col = nbase + nt * 8 + lr;
                    float2 pb = *(float2*)(Bb + col * MS1 + k0 + lc * 2);
                    bfr[nt][0] = __float_as_uint(pb.x);
                    bfr[nt][1] = __float_as_uint(pb.y);
                }
                #pragma unroll
                for (int mt = 0; mt < 2; mt++)
                    #pragma unroll
                    for (int nt = 0; nt < 4; nt++)
                        mma16n8k8(d[mt][nt], afr[mt], bfr[nt]);
            }
            __syncthreads();
        }

        // prefetch W2 chunk 0
        {
            #pragma unroll
            for (int p = 0; p < 4; p++) {
                int idx = tid + (p << 8);
                int n = idx >> 4, q = idx & 15;
                const float* src = g_W2t + ((size_t)e * C + n) * II + q * 4;
                cpa16(sb + OFF_W + n * (MSH * 4) + q * 16, src, true);
            }
            CP_COMMIT();
        }

        // H epilogue -> A region (stride MSH, permuted)
        float* H = (float*)(smem + OFF_A0);
        int pos0 = ((lc & 1) << 2) | (lc >> 1);
        #pragma unroll
        for (int mt = 0; mt < 2; mt++) {
            int r0 = rbase + mt * 16 + lr;
            #pragma unroll
            for (int nt = 0; nt < 4; nt++) {
                int base = nbase + nt * 8;
                H[r0 * MSH + base + pos0]           = to_tf32(gelu_exact(d[mt][nt][0]));
                H[r0 * MSH + base + pos0 + 2]       = to_tf32(gelu_exact(d[mt][nt][1]));
                H[(r0 + 8) * MSH + base + pos0]     = to_tf32(gelu_exact(d[mt][nt][2]));
                H[(r0 + 8) * MSH + base + pos0 + 2] = to_tf32(gelu_exact(d[mt][nt][3]));
            }
        }
    }

    // ---------- phase 2: 8 n-chunks of 64 cols ----------
    float* H = (float*)(smem + OFF_A0);
    float* Wb = (float*)(smem + OFF_W);
    int nbase2 = warpN * 32;

    auto stage2 = [&](int nc) {
        #pragma unroll
        for (int p = 0; p < 4; p++) {
            int idx = tid + (p << 8);
            int n = idx >> 4, q = idx & 15;
            const float* src = g_W2t + ((size_t)e * C + nc * 64 + n) * II + q * 4;
            cpa16(sb + OFF_W + n * (MSH * 4) + q * 16, src, true);
        }
        CP_COMMIT();
    };

    #pragma unroll 1
    for (int nc = 0; nc < 8; nc++) {
        CP_WAIT(0);
        __syncthreads();

        float d2[2][4][4];
        #pragma unroll
        for (int mt = 0; mt < 2; mt++)
            #pragma unroll
            for (int nt = 0; nt < 4; nt++)
                #pragma unroll
                for (int i = 0; i < 4; i++) d2[mt][nt][i] = 0.f;

        #pragma unroll
        for (int ks = 0; ks < 8; ks++) {
            int k0 = ks * 8;
            uint32_t afr[2][4], bfr[4][2];
            #pragma unroll
            for (int mt = 0; mt < 2; mt++) {
                int row = rbase + mt * 16 + lr;
                float2 pa0 = *(float2*)(H + row * MSH + k0 + lc * 2);
                float2 pa1 = *(float2*)(H + (row + 8) * MSH + k0 + lc * 2);
                afr[mt][0] = __float_as_uint(pa0.x);
                afr[mt][1] = __float_as_uint(pa1.x);
                afr[mt][2] = __float_as_uint(pa0.y);
                afr[mt][3] = __float_as_uint(pa1.y);
            }
            #pragma unroll
            for (int nt = 0; nt < 4; nt++) {
                int col = nbase2 + nt * 8 + lr;
                float2 pb = *(float2*)(Wb + col * MSH + k0 + lc * 2);
                bfr[nt][0] = __float_as_uint(pb.x);
                bfr[nt][1] = __float_as_uint(pb.y);
            }
            #pragma unroll
            for (int mt = 0; mt < 2; mt++)
                #pragma unroll
                for (int nt = 0; nt < 4; nt++)
                    mma16n8k8(d2[mt][nt], afr[mt], bfr[nt]);
        }

        __syncthreads();
        if (nc + 1 < 8) stage2(nc + 1);

        #pragma unroll
        for (int mt = 0; mt < 2; mt++) {
            int s0 = rbase + mt * 16 + lr, s1 = s0 + 8;
            int tok0 = toks[s0], tok1 = toks[s1];
            #pragma unroll
            for (int nt = 0; nt < 4; nt++) {
                int col = nc * 64 + nbase2 + nt * 8 + lc * 2;
                if (tok0 >= 0)
                    *(float2*)&feo[((size_t)tok0 * E + e) * C + col] =
                        make_float2(d2[mt][nt][0], d2[mt][nt][1]);
                if (tok1 >= 0)
                    *(float2*)&feo[((size_t)tok1 * E + e) * C + col] =
                        make_float2(d2[mt][nt][2], d2[mt][nt][3]);
            }
        }
    }
}

// ---------------- launch 4: final reduce (R12 version) ----------------
__global__ __launch_bounds__(128) void final_reduce(
    const float* __restrict__ maskp, const float* __restrict__ feo,
    float* __restrict__ final_out) {
    int t = blockIdx.x;
    int tid = threadIdx.x;
    int lane = tid & 31;
    __shared__ float s_w[E];
    __shared__ int   s_ei[E];
    __shared__ int   s_na;

    if (tid < 32) {
        float mv = maskp[(size_t)t * E + lane];
        unsigned act = __ballot_sync(FULLMASK, mv > 0.f);
        int rank = __popc(act & ((1u << lane) - 1u));
        if (mv > 0.f) {
            s_ei[rank] = lane;
            s_w[rank]  = g_rw[t * E + lane];
        }
        if (lane == 0) s_na = __popc(act);
    }
    __syncthreads();

    int na = s_na;
    const float4* base = (const float4*)&feo[(size_t)t * E * C];
    float4 a0 = make_float4(0.f, 0.f, 0.f, 0.f), a1 = a0, a2 = a0, a3 = a0;
    int i = 0;
    for (; i + 4 <= na; i += 4) {
        float w0 = s_w[i], w1 = s_w[i + 1], w2 = s_w[i + 2], w3 = s_w[i + 3];
        float4 v0 = base[s_ei[i]     * 128 + tid];
        float4 v1 = base[s_ei[i + 1] * 128 + tid];
        float4 v2 = base[s_ei[i + 2] * 128 + tid];
        float4 v3 = base[s_ei[i + 3] * 128 + tid];
        a0.x = fmaf(w0, v0.x, a0.x); a0.y = fmaf(w0, v0.y, a0.y);
        a0.z = fmaf(w0, v0.z, a0.z); a0.w = fmaf(w0, v0.w, a0.w);
        a1.x = fmaf(w1, v1.x, a1.x); a1.y = fmaf(w1, v1.y, a1.y);
        a1.z = fmaf(w1, v1.z, a1.z); a1.w = fmaf(w1, v1.w, a1.w);
        a2.x = fmaf(w2, v2.x, a2.x); a2.y = fmaf(w2, v2.y, a2.y);
        a2.z = fmaf(w2, v2.z, a2.z); a2.w = fmaf(w2, v2.w, a2.w);
        a3.x = fmaf(w3, v3.x, a3.x); a3.y = fmaf(w3, v3.y, a3.y);
        a3.z = fmaf(w3, v3.z, a3.z); a3.w = fmaf(w3, v3.w, a3.w);
    }
    for (; i < na; i++) {
        float w0 = s_w[i];
        float4 v0 = base[s_ei[i] * 128 + tid];
        a0.x = fmaf(w0, v0.x, a0.x); a0.y = fmaf(w0, v0.y, a0.y);
        a0.z = fmaf(w0, v0.z, a0.z); a0.w = fmaf(w0, v0.w, a0.w);
    }
    float4 acc;
    acc.x = (a0.x + a1.x) + (a2.x + a3.x);
    acc.y = (a0.y + a1.y) + (a2.y + a3.y);
    acc.z = (a0.z + a1.z) + (a2.z + a3.z);
    acc.w = (a0.w + a1.w) + (a2.w + a3.w);
    ((float4*)&final_out[(size_t)t * C])[tid] = acc;
}

// ---------------- launch ----------------
extern "C" void kernel_launch(void* const* d_in, const int* in_sizes, int n_in,
                              void* d_out, int out_size) {
    const float* x     = (const float*)d_in[0];
    const float* sim   = (const float*)d_in[1];
    const float* gates = (const float*)d_in[2];
    const float* W1    = (const float*)d_in[3];
    const float* W2    = (const float*)d_in[4];

    float* out       = (float*)d_out;
    float* final_out = out;
    float* feo       = out + (size_t)T * C;
    float* pre       = feo + (size_t)T * E * C;
    float* maskp     = pre + (size_t)T * E;

    cudaFuncSetAttribute(expert_mlp, cudaFuncAttributeMaxDynamicSharedMemorySize, EM_SMEM);

    prep_kernel<<<1, 1024>>>(sim, gates);
    fused_pre<<<GB_RX, 256>>>(x, sim, W1, W2, pre, maskp);
    expert_mlp<<<dim3(T / 128 + 1, E), 256, EM_SMEM>>>(feo);
    final_reduce<<<T, 128>>>(maskp, feo, final_out);
}

// round 16
// speedup vs baseline: 1.0511x; 1.0479x over previous
#include <cuda_runtime.h>
#include <cstdint>
#include <math.h>

#define T 8192
#define C 512
#define II 64
#define E 32
#define KFB (E/2)
#define FULLMASK 0xffffffffu
#define NEGC (-3.3895313892515355e+38f)

// ---------------- device scratch ----------------
__device__ float g_rw[T * E];
__device__ int   g_idx[E * T];
__device__ int   g_iidx[E * T];
__device__ int   g_cnt[E];
__device__ int   g_icnt[E];
__device__ float g_colnorm[E];
__device__ float g_sig[E];
__device__ float g_Xp[(size_t)T * C];         // x, tf32-rounded, perm per 8-k group
__device__ float g_W1t[(size_t)E * II * C];   // [e][i][pk]  K-major, tf32, permuted
__device__ float g_W2t[(size_t)E * C * II];   // [e][c][pk]  K-major, tf32, permuted

#define PCOL(k) (((k) & ~7) | ((((k) & 3) << 1) | (((k) >> 2) & 1)))

// ---------------- helpers ----------------
__device__ __forceinline__ float to_tf32(float f) {
    uint32_t u;
    asm("cvt.rna.tf32.f32 %0, %1;" : "=r"(u) : "f"(f));
    return __uint_as_float(u);
}
__device__ __forceinline__ uint32_t smem_u32(const void* p) {
    uint32_t a;
    asm("{ .reg .u64 t; cvta.to.shared.u64 t, %1; cvt.u32.u64 %0, t; }" : "=r"(a) : "l"(p));
    return a;
}
__device__ __forceinline__ void cpa16(uint32_t dst, const void* src, bool valid) {
    int sz = valid ? 16 : 0;
    asm volatile("cp.async.cg.shared.global [%0], [%1], 16, %2;"
                 :: "r"(dst), "l"(src), "r"(sz) : "memory");
}
#define CP_COMMIT() asm volatile("cp.async.commit_group;" ::: "memory")
#define CP_WAIT(n)  asm volatile("cp.async.wait_group %0;" :: "n"(n) : "memory")

// streaming stores/loads for feo (written once, read once -> keep out of L2)
__device__ __forceinline__ void stcs_f2(float* p, float a, float b) {
    asm volatile("st.global.cs.v2.f32 [%0], {%1, %2};" :: "l"(p), "f"(a), "f"(b) : "memory");
}
__device__ __forceinline__ void stcs_f4z(float* p) {
    asm volatile("st.global.cs.v4.f32 [%0], {%1, %1, %1, %1};" :: "l"(p), "f"(0.f) : "memory");
}
__device__ __forceinline__ float4 ldcs_f4(const float4* p) {
    float4 v;
    asm volatile("ld.global.cs.v4.f32 {%0, %1, %2, %3}, [%4];"
                 : "=f"(v.x), "=f"(v.y), "=f"(v.z), "=f"(v.w) : "l"(p));
    return v;
}

__device__ __forceinline__ void mma16n8k8(float* d, const uint32_t* a, const uint32_t* b) {
    asm volatile(
        "mma.sync.aligned.m16n8k8.row.col.f32.tf32.tf32.f32 "
        "{%0,%1,%2,%3}, {%4,%5,%6,%7}, {%8,%9}, {%0,%1,%2,%3};"
        : "+f"(d[0]), "+f"(d[1]), "+f"(d[2]), "+f"(d[3])
        : "r"(a[0]), "r"(a[1]), "r"(a[2]), "r"(a[3]), "r"(b[0]), "r"(b[1]));
}

__device__ __forceinline__ float gelu_exact(float v) {
    return 0.5f * v * (1.0f + erff(v * 0.70710678118654752f));
}

// ---------------- launch 1: prep ----------------
__global__ void prep_kernel(const float* __restrict__ sim, const float* __restrict__ gates) {
    int w = threadIdx.x >> 5;
    int lane = threadIdx.x & 31;
    float s = 0.f;
    for (int c = lane; c < C; c += 32) {
        float v = sim[c * E + w];
        s = fmaf(v, v, s);
    }
    #pragma unroll
    for (int o = 16; o; o >>= 1) s += __shfl_xor_sync(FULLMASK, s, o);
    if (lane == 0) {
        g_colnorm[w] = fmaxf(sqrtf(s), 1e-12f);
        g_sig[w]     = 1.f / (1.f + expf(-gates[w]));
        g_cnt[w]     = 0;
        g_icnt[w]    = 0;
    }
}

// ---------------- launch 2: fused preprocessing megakernel ----------------
#define GB_GATE 1024
#define GB_TW1  (GB_GATE + 1024)
#define GB_TW2  (GB_TW1 + 1024)
#define GB_RX   (GB_TW2 + 4096)

__global__ __launch_bounds__(256) void fused_pre(
    const float* __restrict__ x, const float* __restrict__ sim,
    const float* __restrict__ W1, const float* __restrict__ W2,
    float* __restrict__ pre_out, float* __restrict__ mask_out) {
    __shared__ float s_x[8 * C];
    __shared__ unsigned char s_act[8][E];

    int b = blockIdx.x;
    int tid = threadIdx.x;

    if (b >= GB_TW2) {
        // round_x role
        int b2 = b - GB_TW2;
        int t = b2 * 2 + (tid >> 7);
        int c = (tid & 127) * 4;
        float4 v = *(const float4*)(x + (size_t)t * C + c);
        float* dst = g_Xp + (size_t)t * C;
        dst[PCOL(c)]     = to_tf32(v.x);
        dst[PCOL(c + 1)] = to_tf32(v.y);
        dst[PCOL(c + 2)] = to_tf32(v.z);
        dst[PCOL(c + 3)] = to_tf32(v.w);
        return;
    }
    if (b >= GB_GATE) {
        // weight transpose roles
        float (*t)[33] = (float(*)[33])s_x;
        int tx = tid & 31, ty = tid >> 5;
        if (b < GB_TW1) {
            int b2 = b - GB_GATE;
            int c0 = (b2 & 15) * 32, i0 = ((b2 >> 4) & 1) * 32, e = b2 >> 5;
            #pragma unroll
            for (int j = 0; j < 32; j += 8)
                t[ty + j][tx] = W1[((size_t)e * C + c0 + ty + j) * II + i0 + tx];
            __syncthreads();
            #pragma unroll
            for (int j = 0; j < 32; j += 8)
                g_W1t[((size_t)e * II + i0 + ty + j) * C + PCOL(c0 + tx)] = to_tf32(t[tx][ty + j]);
        } else {
            int b2 = b - GB_TW1;
            int i0 = (b2 & 1) * 32, c0 = ((b2 >> 1) & 15) * 32, e = b2 >> 5;
            #pragma unroll
            for (int j = 0; j < 32; j += 8)
                t[ty + j][tx] = W2[((size_t)e * II + i0 + ty + j) * C + c0 + tx];
            __syncthreads();
            #pragma unroll
            for (int j = 0; j < 32; j += 8)
                g_W2t[((size_t)e * C + c0 + ty + j) * II + PCOL(i0 + tx)] = to_tf32(t[tx][ty + j]);
        }
        return;
    }

    // gating role
    int w = tid >> 5;
    int lane = tid & 31;
    int t0 = b * 8;
    int t = t0 + w;

    const float* xbase = x + (size_t)t0 * C;
    #pragma unroll
    for (int p = 0; p < 16; p++) s_x[tid + p * 256] = xbase[tid + p * 256];
    __syncthreads();

    const float* xw = s_x + w * C;
    float acc = 0.f, nsq = 0.f;
    #pragma unroll 8
    for (int c = 0; c < C; c++) {
        float xc = xw[c];
        acc = fmaf(xc, __ldg(&sim[c * E + lane]), acc);
        nsq = fmaf(xc, xc, nsq);
    }

    float xnorm = fmaxf(sqrtf(nsq), 1e-12f);
    float logit = acc / (xnorm * g_colnorm[lane]);
    float pre   = logit - g_sig[lane];
    float gated = fmaxf(pre, 0.f);

    unsigned act = __ballot_sync(FULLMASK, gated > 0.f);
    float maskv;
    if (act == 0u) {
        int rank = 0;
        #pragma unroll
        for (int j = 0; j < 32; j++) {
            float lj = __shfl_sync(FULLMASK, logit, j);
            rank += (lj > logit) || (lj == logit && j < lane);
        }
        maskv = (rank < KFB) ? 1.f : 0.f;
    } else {
        maskv = (gated > 0.f) ? 1.f : 0.f;
    }

    float maskedv = (maskv > 0.f) ? gated : NEGC;
    float m = maskedv;
    #pragma unroll
    for (int o = 16; o; o >>= 1) m = fmaxf(m, __shfl_xor_sync(FULLMASK, m, o));
    float p = expf(maskedv - m);
    float ssum = p;
    #pragma unroll
    for (int o = 16; o; o >>= 1) ssum += __shfl_xor_sync(FULLMASK, ssum, o);
    float rw = p / ssum;

    pre_out[t * E + lane]  = pre;
    mask_out[t * E + lane] = maskv;
    g_rw[t * E + lane]     = rw;
    s_act[w][lane] = (maskv > 0.f) ? 1 : 0;
    __syncthreads();

    if (tid < E) {
        int e = tid;
        int cntl = 0;
        #pragma unroll
        for (int s2 = 0; s2 < 8; s2++) cntl += s_act[s2][e];
        if (cntl > 0) {
            int base = atomicAdd(&g_cnt[e], cntl);
            for (int s2 = 0; s2 < 8; s2++)
                if (s_act[s2][e]) g_idx[e * T + base++] = t0 + s2;
        }
        if (cntl < 8) {
            int ibase = atomicAdd(&g_icnt[e], 8 - cntl);
            for (int s2 = 0; s2 < 8; s2++)
                if (!s_act[s2][e]) g_iidx[e * T + ibase++] = t0 + s2;
        }
    }
}

// ---------------- launch 3: fused expert MLP (R12 winner + streaming feo stores) --
#define MS1 40
#define MSH 72
#define XBUF_B (128 * MS1 * 4)              // 20480
#define W1BUF_B (64 * MS1 * 4)              // 10240
#define OFF_A0 1024
#define OFF_W  (1024 + 2 * XBUF_B)          // 41984
#define EM_SMEM (OFF_W + 2 * W1BUF_B)       // 62464

__global__ __launch_bounds__(256, 3) void expert_mlp(float* __restrict__ feo) {
    int e = blockIdx.y;
    int cnt = g_cnt[e];
    int cntB = (cnt + 127) >> 7;
    int tid = threadIdx.x;

    extern __shared__ char smem[];
    int* toks = (int*)smem;

    if ((int)blockIdx.x >= cntB) {
        // zero path: inactive rows (streaming stores)
        int icnt = g_icnt[e];
        int zi0 = ((int)blockIdx.x - cntB) * 128;
        if (zi0 >= icnt) return;
        int nrows = min(128, icnt - zi0);
        if (tid < nrows) toks[tid] = g_iidx[e * T + zi0 + tid];
        __syncthreads();
        for (int j = tid; j < nrows * 128; j += 256) {
            int r = j >> 7, q = j & 127;
            stcs_f4z(&feo[((size_t)toks[r] * E + e) * C + q * 4]);
        }
        return;
    }

    int m0 = blockIdx.x * 128;
    uint32_t sb = smem_u32(smem);
    int wid = tid >> 5, lane = tid & 31;
    if (tid < 128) toks[tid] = (m0 + tid < cnt) ? g_idx[e * T + m0 + tid] : -1;
    __syncthreads();

    int warpM = wid >> 1, warpN = wid & 1;
    int rbase = warpM * 32;
    int lr = lane >> 2, lc = lane & 3;

    uint32_t aoff[2] = { sb + OFF_A0, sb + OFF_A0 + XBUF_B };
    uint32_t boff[2] = { sb + OFF_W, sb + OFF_W + W1BUF_B };

    auto stage1 = [&](int kc, int b) {
        #pragma unroll
        for (int p = 0; p < 4; p++) {
            int idx = tid + (p << 8);
            int r = idx >> 3, q = idx & 7;
            int tok = toks[r];
            const float* src = g_Xp + (size_t)(tok < 0 ? 0 : tok) * C + kc * 32 + q * 4;
            cpa16(aoff[b] + r * (MS1 * 4) + q * 16, src, tok >= 0);
        }
        #pragma unroll
        for (int p = 0; p < 2; p++) {
            int idx = tid + (p << 8);
            int i = idx >> 3, q = idx & 7;
            const float* src = g_W1t + ((size_t)e * II + i) * C + kc * 32 + q * 4;
            cpa16(boff[b] + i * (MS1 * 4) + q * 16, src, true);
        }
        CP_COMMIT();
    };

    // ---------- phase 1: 16 k-chunks of 32, double-buffered ----------
    {
        int nbase = warpN * 32;
        float d[2][4][4];
        #pragma unroll
        for (int mt = 0; mt < 2; mt++)
            #pragma unroll
            for (int nt = 0; nt < 4; nt++)
                #pragma unroll
                for (int i = 0; i < 4; i++) d[mt][nt][i] = 0.f;

        stage1(0, 0);
        #pragma unroll 1
        for (int kc = 0; kc < 16; kc++) {
            if (kc + 1 < 16) { stage1(kc + 1, (kc + 1) & 1); CP_WAIT(1); }
            else             { CP_WAIT(0); }
            __syncthreads();

            float* Ab = (float*)(smem + OFF_A0 + (kc & 1) * XBUF_B);
            float* Bb = (float*)(smem + OFF_W + (kc & 1) * W1BUF_B);

            #pragma unroll
            for (int ks = 0; ks < 4; ks++) {
                int k0 = ks * 8;
                uint32_t afr[2][4], bfr[4][2];
                #pragma unroll
                for (int mt = 0; mt < 2; mt++) {
                    int row = rbase + mt * 16 + lr;
                    float2 pa0 = *(float2*)(Ab + row * MS1 + k0 + lc * 2);
                    float2 pa1 = *(float2*)(Ab + (row + 8) * MS1 + k0 + lc * 2);
                    afr[mt][0] = __float_as_uint(pa0.x);
                    afr[mt][1] = __float_as_uint(pa1.x);
                    afr[mt][2] = __float_as_uint(pa0.y);
                    afr[mt][3] = __float_as_uint(pa1.y);
                }
                #pragma unroll
                for (int nt = 0; nt < 4; nt++) {
                    int col = nbase + nt * 8 + lr;
                    float2 pb = *(float2*)(Bb + col * MS1 + k0 + lc * 2);
                    bfr[nt][0] = __float_as_uint(pb.x);
                    bfr[nt][1] = __float_as_uint(pb.y);
                }
                #pragma unroll
                for (int mt = 0; mt < 2; mt++)
                    #pragma unroll
                    for (int nt = 0; nt < 4; nt++)
                        mma16n8k8(d[mt][nt], afr[mt], bfr[nt]);
            }
            __syncthreads();
        }

        // prefetch W2 chunk 0
        {
            #pragma unroll
            for (int p = 0; p < 4; p++) {
                int idx = tid + (p << 8);
                int n = idx >> 4, q = idx & 15;
                const float* src = g_W2t + ((size_t)e * C + n) * II + q * 4;
                cpa16(sb + OFF_W + n * (MSH * 4) + q * 16, src, true);
            }
            CP_COMMIT();
        }

        // H epilogue -> A region (stride MSH, permuted)
        float* H = (float*)(smem + OFF_A0);
        int pos0 = ((lc & 1) << 2) | (lc >> 1);
        #pragma unroll
        for (int mt = 0; mt < 2; mt++) {
            int r0 = rbase + mt * 16 + lr;
            #pragma unroll
            for (int nt = 0; nt < 4; nt++) {
                int base = nbase + nt * 8;
                H[r0 * MSH + base + pos0]           = to_tf32(gelu_exact(d[mt][nt][0]));
                H[r0 * MSH + base + pos0 + 2]       = to_tf32(gelu_exact(d[mt][nt][1]));
                H[(r0 + 8) * MSH + base + pos0]     = to_tf32(gelu_exact(d[mt][nt][2]));
                H[(r0 + 8) * MSH + base + pos0 + 2] = to_tf32(gelu_exact(d[mt][nt][3]));
            }
        }
    }

    // ---------- phase 2: 8 n-chunks of 64 cols ----------
    float* H = (float*)(smem + OFF_A0);
    float* Wb = (float*)(smem + OFF_W);
    int nbase2 = warpN * 32;

    auto stage2 = [&](int nc) {
        #pragma unroll
        for (int p = 0; p < 4; p++) {
            int idx = tid + (p << 8);
            int n = idx >> 4, q = idx & 15;
            const float* src = g_W2t + ((size_t)e * C + nc * 64 + n) * II + q * 4;
            cpa16(sb + OFF_W + n * (MSH * 4) + q * 16, src, true);
        }
        CP_COMMIT();
    };

    #pragma unroll 1
    for (int nc = 0; nc < 8; nc++) {
        CP_WAIT(0);
        __syncthreads();

        float d2[2][4][4];
        #pragma unroll
        for (int mt = 0; mt < 2; mt++)
            #pragma unroll
            for (int nt = 0; nt < 4; nt++)
                #pragma unroll
                for (int i = 0; i < 4; i++) d2[mt][nt][i] = 0.f;

        #pragma unroll
        for (int ks = 0; ks < 8; ks++) {
            int k0 = ks * 8;
            uint32_t afr[2][4], bfr[4][2];
            #pragma unroll
            for (int mt = 0; mt < 2; mt++) {
                int row = rbase + mt * 16 + lr;
                float2 pa0 = *(float2*)(H + row * MSH + k0 + lc * 2);
                float2 pa1 = *(float2*)(H + (row + 8) * MSH + k0 + lc * 2);
                afr[mt][0] = __float_as_uint(pa0.x);
                afr[mt][1] = __float_as_uint(pa1.x);
                afr[mt][2] = __float_as_uint(pa0.y);
                afr[mt][3] = __float_as_uint(pa1.y);
            }
            #pragma unroll
            for (int nt = 0; nt < 4; nt++) {
                int col = nbase2 + nt * 8 + lr;
                float2 pb = *(float2*)(Wb + col * MSH + k0 + lc * 2);
                bfr[nt][0] = __float_as_uint(pb.x);
                bfr[nt][1] = __float_as_uint(pb.y);
            }
            #pragma unroll
            for (int mt = 0; mt < 2; mt++)
                #pragma unroll
                for (int nt = 0; nt < 4; nt++)
                    mma16n8k8(d2[mt][nt], afr[mt], bfr[nt]);
        }

        __syncthreads();
        if (nc + 1 < 8) stage2(nc + 1);

        #pragma unroll
        for (int mt = 0; mt < 2; mt++) {
            int s0 = rbase + mt * 16 + lr, s1 = s0 + 8;
            int tok0 = toks[s0], tok1 = toks[s1];
            #pragma unroll
            for (int nt = 0; nt < 4; nt++) {
                int col = nc * 64 + nbase2 + nt * 8 + lc * 2;
                if (tok0 >= 0)
                    stcs_f2(&feo[((size_t)tok0 * E + e) * C + col],
                            d2[mt][nt][0], d2[mt][nt][1]);
                if (tok1 >= 0)
                    stcs_f2(&feo[((size_t)tok1 * E + e) * C + col],
                            d2[mt][nt][2], d2[mt][nt][3]);
            }
        }
    }
}

// ---------------- launch 4: final reduce (R12 + streaming feo reads) --------------
__global__ __launch_bounds__(128) void final_reduce(
    const float* __restrict__ maskp, const float* __restrict__ feo,
    float* __restrict__ final_out) {
    int t = blockIdx.x;
    int tid = threadIdx.x;
    int lane = tid & 31;
    __shared__ float s_w[E];
    __shared__ int   s_ei[E];
    __shared__ int   s_na;

    if (tid < 32) {
        float mv = maskp[(size_t)t * E + lane];
        unsigned act = __ballot_sync(FULLMASK, mv > 0.f);
        int rank = __popc(act & ((1u << lane) - 1u));
        if (mv > 0.f) {
            s_ei[rank] = lane;
            s_w[rank]  = g_rw[t * E + lane];
        }
        if (lane == 0) s_na = __popc(act);
    }
    __syncthreads();

    int na = s_na;
    const float4* base = (const float4*)&feo[(size_t)t * E * C];
    float4 a0 = make_float4(0.f, 0.f, 0.f, 0.f), a1 = a0, a2 = a0, a3 = a0;
    int i = 0;
    for (; i + 4 <= na; i += 4) {
        float w0 = s_w[i], w1 = s_w[i + 1], w2 = s_w[i + 2], w3 = s_w[i + 3];
        float4 v0 = ldcs_f4(&base[s_ei[i]     * 128 + tid]);
        float4 v1 = ldcs_f4(&base[s_ei[i + 1] * 128 + tid]);
        float4 v2 = ldcs_f4(&base[s_ei[i + 2] * 128 + tid]);
        float4 v3 = ldcs_f4(&base[s_ei[i + 3] * 128 + tid]);
        a0.x = fmaf(w0, v0.x, a0.x); a0.y = fmaf(w0, v0.y, a0.y);
        a0.z = fmaf(w0, v0.z, a0.z); a0.w = fmaf(w0, v0.w, a0.w);
        a1.x = fmaf(w1, v1.x, a1.x); a1.y = fmaf(w1, v1.y, a1.y);
        a1.z = fmaf(w1, v1.z, a1.z); a1.w = fmaf(w1, v1.w, a1.w);
        a2.x = fmaf(w2, v2.x, a2.x); a2.y = fmaf(w2, v2.y, a2.y);
        a2.z = fmaf(w2, v2.z, a2.z); a2.w = fmaf(w2, v2.w, a2.w);
        a3.x = fmaf(w3, v3.x, a3.x); a3.y = fmaf(w3, v3.y, a3.y);
        a3.z = fmaf(w3, v3.z, a3.z); a3.w = fmaf(w3, v3.w, a3.w);
    }
    for (; i < na; i++) {
        float w0 = s_w[i];
        float4 v0 = ldcs_f4(&base[s_ei[i] * 128 + tid]);
        a0.x = fmaf(w0, v0.x, a0.x); a0.y = fmaf(w0, v0.y, a0.y);
        a0.z = fmaf(w0, v0.z, a0.z); a0.w = fmaf(w0, v0.w, a0.w);
    }
    float4 acc;
    acc.x = (a0.x + a1.x) + (a2.x + a3.x);
    acc.y = (a0.y + a1.y) + (a2.y + a3.y);
    acc.z = (a0.z + a1.z) + (a2.z + a3.z);
    acc.w = (a0.w + a1.w) + (a2.w + a3.w);
    ((float4*)&final_out[(size_t)t * C])[tid] = acc;
}

// ---------------- launch ----------------
extern "C" void kernel_launch(void* const* d_in, const int* in_sizes, int n_in,
                              void* d_out, int out_size) {
    const float* x     = (const float*)d_in[0];
    const float* sim   = (const float*)d_in[1];
    const float* gates = (const float*)d_in[2];
    const float* W1    = (const float*)d_in[3];
    const float* W2    = (const float*)d_in[4];

    float* out       = (float*)d_out;
    float* final_out = out;
    float* feo       = out + (size_t)T * C;
    float* pre       = feo + (size_t)T * E * C;
    float* maskp     = pre + (size_t)T * E;

    cudaFuncSetAttribute(expert_mlp, cudaFuncAttributeMaxDynamicSharedMemorySize, EM_SMEM);

    prep_kernel<<<1, 1024>>>(sim, gates);
    fused_pre<<<GB_RX, 256>>>(x, sim, W1, W2, pre, maskp);
    expert_mlp<<<dim3(T / 128 + 1, E), 256, EM_SMEM>>>(feo);
    final_reduce<<<T, 128>>>(maskp, feo, final_out);
}